// round 2
// baseline (speedup 1.0000x reference)
#include <cuda_runtime.h>
#include <math.h>

#define B_ 8
#define C_ 512
#define H_ 64
#define W_ 128
#define K_ 19
#define N_ 8
#define CI_ 256
#define HW_ (H_*W_)       // 8192
#define KC_ (K_*C_)       // 9728
#define ROWS_ (B_*N_*K_)  // 1216

// ---------------- scratch (static device globals; no allocs) ----------------
__device__ float g_cam[B_*K_*HW_];        // [b,k,h*w]
__device__ float g_mx[ROWS_];             // per (b,n,k) max of cam over bin
__device__ float g_coef[ROWS_];           // sigmoid(mean)/sumexp
__device__ float g_local[B_*N_*KC_];      // [b,n,k,c]
__device__ float g_t[B_*N_*KC_];          // gcn conv1 + prelu
__device__ float g_l2[B_*N_*KC_];         // gcn linear out
__device__ float g_glob[B_*KC_];          // [b,k,c]
__device__ float g_key[ROWS_*CI_];        // [b,n,k,i]
__device__ float g_qk[B_*N_*KC_];         // q_w^T @ key  -> [b,n,k,c]
__device__ float g_qbk[ROWS_];            // q_b . key
__device__ float g_val[B_*K_*CI_];        // [b,k,i]
__device__ float g_wv[B_*KC_];            // out_w @ val -> [b,k,c]
__device__ float g_y[B_*C_*HW_];          // pre-BN output (134 MB)
__device__ float g_bnA[C_];
__device__ float g_bnB[C_];

// ---------------- kernel A: cam = conv_cam_w @ x + b ----------------
// 128 blocks: b = blk>>4 (8 batches), 16 chunks of 512 pixels, 2 px/thread.
__global__ __launch_bounds__(256) void k_cam(const float* __restrict__ x,
                                             const float* __restrict__ w,
                                             const float* __restrict__ bias) {
    __shared__ float sw[KC_];
    for (int i = threadIdx.x; i < KC_; i += 256) sw[i] = w[i];
    __syncthreads();
    int b = blockIdx.x >> 4;
    int pix0 = ((blockIdx.x & 15) << 9) + threadIdx.x;
    const float* xp = x + (size_t)b * C_ * HW_ + pix0;
    float acc[K_][2];
#pragma unroll
    for (int k = 0; k < K_; k++) { acc[k][0] = 0.f; acc[k][1] = 0.f; }
    for (int c = 0; c < C_; c++) {
        float x0 = xp[0], x1 = xp[256];
        xp += HW_;
#pragma unroll
        for (int k = 0; k < K_; k++) {
            float wv = sw[k * C_ + c];
            acc[k][0] = fmaf(wv, x0, acc[k][0]);
            acc[k][1] = fmaf(wv, x1, acc[k][1]);
        }
    }
    float* cp = g_cam + (size_t)b * K_ * HW_ + pix0;
#pragma unroll
    for (int k = 0; k < K_; k++) {
        float bv = bias[k];
        cp[k * HW_ +   0] = acc[k][0] + bv;
        cp[k * HW_ + 256] = acc[k][1] + bv;
    }
}

// ---------------- kernel B: per-(b,n,k) bin stats ----------------
__global__ __launch_bounds__(256) void k_binstats() {
    int idx = blockIdx.x;           // bn*19 + k
    int k = idx % K_;
    int bn = idx / K_;
    int n = bn & 7, b = bn >> 3;
    int bh = n >> 2, bw = n & 3;
    int base = (b * K_ + k) * HW_ + bh * 32 * W_ + bw * 32;
    __shared__ float s[1024];
    __shared__ float red[256];
    int tid = threadIdx.x;
    for (int i = tid; i < 1024; i += 256)
        s[i] = g_cam[base + (i >> 5) * W_ + (i & 31)];
    __syncthreads();
    float sm = 0.f, mx = -1e30f;
    for (int i = tid; i < 1024; i += 256) { float v = s[i]; sm += v; mx = fmaxf(mx, v); }
    red[tid] = sm; __syncthreads();
    for (int o = 128; o > 0; o >>= 1) { if (tid < o) red[tid] += red[tid + o]; __syncthreads(); }
    float total = red[0]; __syncthreads();
    red[tid] = mx; __syncthreads();
    for (int o = 128; o > 0; o >>= 1) { if (tid < o) red[tid] = fmaxf(red[tid], red[tid + o]); __syncthreads(); }
    mx = red[0]; __syncthreads();
    float se = 0.f;
    for (int i = tid; i < 1024; i += 256) se += expf(s[i] - mx);
    red[tid] = se; __syncthreads();
    for (int o = 128; o > 0; o >>= 1) { if (tid < o) red[tid] += red[tid + o]; __syncthreads(); }
    if (tid == 0) {
        float mean = total * (1.f / 1024.f);
        float conf = 1.f / (1.f + expf(-mean));   // sigmoid(mean)
        g_mx[idx] = mx;
        g_coef[idx] = conf / red[0];              // bin_conf / sumexp
    }
}

// ---------------- kernel C: local[b,n,k,c] = sum_p pixw * x ----------------
__global__ __launch_bounds__(256) void k_local(const float* __restrict__ x) {
    int blk = blockIdx.x;            // 128 blocks: bn*2 + half
    int half = blk & 1, bn = blk >> 1;
    int n = bn & 7, b = bn >> 3;
    int bh = n >> 2, bw = n & 3;
    int c0 = half * 256;
    int tid = threadIdx.x;
    __shared__ float Xs[256 * 34];
    __shared__ float Pe[K_ * 32];
    __shared__ float smx[K_], scf[K_];
    if (tid < K_) { smx[tid] = g_mx[bn * K_ + tid]; scf[tid] = g_coef[bn * K_ + tid]; }
    float acc[K_];
#pragma unroll
    for (int k = 0; k < K_; k++) acc[k] = 0.f;
    const float* xb = x + (size_t)b * C_ * HW_;
    for (int chunk = 0; chunk < 32; chunk++) {
        int rowpix = (bh * 32 + chunk) * W_ + bw * 32;
        __syncthreads();
        for (int i = tid; i < 256 * 32; i += 256) {
            int c = i >> 5, p = i & 31;
            Xs[c * 34 + p] = xb[(size_t)(c0 + c) * HW_ + rowpix + p];
        }
        for (int i = tid; i < K_ * 32; i += 256) {
            int k = i >> 5, p = i & 31;
            Pe[i] = expf(g_cam[(b * K_ + k) * HW_ + rowpix + p] - smx[k]) * scf[k];
        }
        __syncthreads();
#pragma unroll 4
        for (int p = 0; p < 32; p += 2) {
            float2 xv = *(const float2*)&Xs[tid * 34 + p];
#pragma unroll
            for (int k = 0; k < K_; k++) {
                float2 pv = *(const float2*)&Pe[k * 32 + p];
                acc[k] = fmaf(pv.x, xv.x, acc[k]);
                acc[k] = fmaf(pv.y, xv.y, acc[k]);
            }
        }
    }
    float* lp = g_local + (size_t)bn * KC_ + c0 + tid;
#pragma unroll
    for (int k = 0; k < K_; k++) lp[k * C_] = acc[k];
}

// ---------------- kernel: GCN conv1 (over bins) + PReLU ----------------
__global__ void k_gcn1(const float* __restrict__ w1, const float* __restrict__ ga) {
    int idx = blockIdx.x * blockDim.x + threadIdx.x;
    if (idx >= B_ * KC_) return;
    int b = idx / KC_, r = idx % KC_;
    float lv[N_];
#pragma unroll
    for (int m = 0; m < N_; m++) lv[m] = g_local[(size_t)(b * N_ + m) * KC_ + r];
#pragma unroll
    for (int nn = 0; nn < N_; nn++) {
        float s = lv[nn];
#pragma unroll
        for (int m = 0; m < N_; m++) s = fmaf(__ldg(&w1[nn * N_ + m]), lv[m], s);
        float a = __ldg(&ga[nn]);
        g_t[(size_t)(b * N_ + nn) * KC_ + r] = s >= 0.f ? s : a * s;
    }
}

// ---------------- generic tiled SGEMM: C[M,N] = A[M,K] * op(B) (+bias) ----------------
// TRANSB=false: C[r,j] = sum_k A[r,k]*B[j*K+k]   (dot of rows)
// TRANSB=true:  C[r,j] = sum_k A[r,k]*B[k*N+j]
template <bool TRANSB, bool HASBIAS>
__global__ __launch_bounds__(256) void k_sgemm(const float* __restrict__ A,
                                               const float* __restrict__ Bm,
                                               const float* __restrict__ bias,
                                               float* __restrict__ Cm,
                                               int M, int N, int K) {
    __shared__ float As[16 * 64];
    __shared__ float Bs[16 * 64];
    int tid = threadIdx.x;
    int bm = blockIdx.y * 64, bn = blockIdx.x * 64;
    int tx = tid & 15, ty = tid >> 4;
    float acc[4][4];
#pragma unroll
    for (int i = 0; i < 4; i++)
#pragma unroll
        for (int j = 0; j < 4; j++) acc[i][j] = 0.f;
    for (int k0 = 0; k0 < K; k0 += 16) {
        {
            int r = tid >> 2, kk = (tid & 3) << 2;
            float4 v = make_float4(0.f, 0.f, 0.f, 0.f);
            if (bm + r < M) v = *(const float4*)&A[(size_t)(bm + r) * K + k0 + kk];
            As[(kk + 0) * 64 + r] = v.x; As[(kk + 1) * 64 + r] = v.y;
            As[(kk + 2) * 64 + r] = v.z; As[(kk + 3) * 64 + r] = v.w;
        }
        if (!TRANSB) {
            int r = tid >> 2, kk = (tid & 3) << 2;
            float4 v = *(const float4*)&Bm[(size_t)(bn + r) * K + k0 + kk];
            Bs[(kk + 0) * 64 + r] = v.x; Bs[(kk + 1) * 64 + r] = v.y;
            Bs[(kk + 2) * 64 + r] = v.z; Bs[(kk + 3) * 64 + r] = v.w;
        } else {
            int kk = tid >> 4, j = (tid & 15) << 2;
            float4 v = *(const float4*)&Bm[(size_t)(k0 + kk) * N + bn + j];
            *(float4*)&Bs[kk * 64 + j] = v;
        }
        __syncthreads();
#pragma unroll
        for (int kk = 0; kk < 16; kk++) {
            float4 a4 = *(const float4*)&As[kk * 64 + ty * 4];
            float4 b4 = *(const float4*)&Bs[kk * 64 + tx * 4];
            float av[4] = {a4.x, a4.y, a4.z, a4.w};
            float bv[4] = {b4.x, b4.y, b4.z, b4.w};
#pragma unroll
            for (int i = 0; i < 4; i++)
#pragma unroll
                for (int j = 0; j < 4; j++) acc[i][j] = fmaf(av[i], bv[j], acc[i][j]);
        }
        __syncthreads();
    }
#pragma unroll
    for (int i = 0; i < 4; i++) {
        int r = bm + ty * 4 + i;
        if (r < M) {
#pragma unroll
            for (int j = 0; j < 4; j++) {
                int cc = bn + tx * 4 + j;
                float v = acc[i][j];
                if (HASBIAS) v += bias[cc];
                Cm[(size_t)r * N + cc] = v;
            }
        }
    }
}

// ---------------- glob = prelu(fuse_w . l2 + fuse_b) ----------------
__global__ void k_glob(const float* __restrict__ fw, const float* __restrict__ fb,
                       const float* __restrict__ ra) {
    int idx = blockIdx.x * blockDim.x + threadIdx.x;
    if (idx >= B_ * KC_) return;
    int b = idx / KC_, r = idx % KC_;
    float s = __ldg(&fb[0]);
#pragma unroll
    for (int nn = 0; nn < N_; nn++)
        s = fmaf(__ldg(&fw[nn]), g_l2[(size_t)(b * N_ + nn) * KC_ + r], s);
    float a = __ldg(&ra[0]);
    g_glob[idx] = s >= 0.f ? s : a * s;
}

// ---------------- qbk[row] = q_b . key[row] ----------------
__global__ __launch_bounds__(256) void k_qbk(const float* __restrict__ qb) {
    int row = blockIdx.x;
    int tid = threadIdx.x;
    __shared__ float red[256];
    red[tid] = qb[tid] * g_key[(size_t)row * CI_ + tid];
    __syncthreads();
    for (int o = 128; o > 0; o >>= 1) { if (tid < o) red[tid] += red[tid + o]; __syncthreads(); }
    if (tid == 0) g_qbk[row] = red[0];
}

// ---------------- fused per-pixel attention: logits->softmax->y ----------------
extern __shared__ float dynsh[];
__global__ __launch_bounds__(256) void k_attn(const float* __restrict__ x) {
    float* qks = dynsh;           // KC_ floats
    float* wvs = dynsh + KC_;     // KC_ floats
    __shared__ float sqb[K_];
    int blk = blockIdx.x;         // 128 blocks: bn*2 + half
    int half = blk & 1, bn = blk >> 1;
    int n = bn & 7, b = bn >> 3;
    int bh = n >> 2, bw = n & 3;
    int tid = threadIdx.x;
    for (int i = tid; i < KC_; i += 256) {
        qks[i] = g_qk[(size_t)bn * KC_ + i];
        wvs[i] = g_wv[(size_t)b * KC_ + i];
    }
    if (tid < K_) sqb[tid] = g_qbk[bn * K_ + tid];
    __syncthreads();
    int p0 = half * 512 + tid;
    int pix0 = (bh * 32 + (p0 >> 5)) * W_ + bw * 32 + (p0 & 31);
    int pix1 = pix0 + 1024;       // p0+256 is 8 rows below
    const float* xb = x + (size_t)b * C_ * HW_;
    float l0[K_], l1[K_];
#pragma unroll
    for (int k = 0; k < K_; k++) { l0[k] = sqb[k]; l1[k] = sqb[k]; }
    for (int c = 0; c < C_; c++) {
        float x0 = xb[(size_t)c * HW_ + pix0];
        float x1 = xb[(size_t)c * HW_ + pix1];
#pragma unroll
        for (int k = 0; k < K_; k++) {
            float w = qks[k * C_ + c];
            l0[k] = fmaf(w, x0, l0[k]);
            l1[k] = fmaf(w, x1, l1[k]);
        }
    }
    float m0 = l0[0], m1 = l1[0];
#pragma unroll
    for (int k = 1; k < K_; k++) { m0 = fmaxf(m0, l0[k]); m1 = fmaxf(m1, l1[k]); }
    float s0 = 0.f, s1 = 0.f;
#pragma unroll
    for (int k = 0; k < K_; k++) {
        l0[k] = expf(l0[k] - m0); s0 += l0[k];
        l1[k] = expf(l1[k] - m1); s1 += l1[k];
    }
    float i0 = 1.f / s0, i1 = 1.f / s1;
#pragma unroll
    for (int k = 0; k < K_; k++) { l0[k] *= i0; l1[k] *= i1; }
    float* yb = g_y + (size_t)b * C_ * HW_;
    for (int c = 0; c < C_; c++) {
        float y0 = 0.f, y1 = 0.f;
#pragma unroll
        for (int k = 0; k < K_; k++) {
            float w = wvs[k * C_ + c];
            y0 = fmaf(l0[k], w, y0);
            y1 = fmaf(l1[k], w, y1);
        }
        yb[(size_t)c * HW_ + pix0] = y0;
        yb[(size_t)c * HW_ + pix1] = y1;
    }
}

// ---------------- BN stats (fp64 accumulation) ----------------
__global__ __launch_bounds__(256) void k_bnstats(const float* __restrict__ gamma,
                                                 const float* __restrict__ beta) {
    int c = blockIdx.x, tid = threadIdx.x;
    double s = 0.0, q = 0.0;
    for (int b = 0; b < B_; b++) {
        const float* yp = g_y + (size_t)(b * C_ + c) * HW_;
        for (int i = tid; i < HW_; i += 256) {
            float v = yp[i];
            s += v; q += (double)v * v;
        }
    }
    __shared__ double rs[256], rq[256];
    rs[tid] = s; rq[tid] = q;
    __syncthreads();
    for (int o = 128; o > 0; o >>= 1) {
        if (tid < o) { rs[tid] += rs[tid + o]; rq[tid] += rq[tid + o]; }
        __syncthreads();
    }
    if (tid == 0) {
        double cnt = (double)(B_ * HW_);
        double mu = rs[0] / cnt;
        double var = rq[0] / cnt - mu * mu;
        double inv = 1.0 / sqrt(var + 1e-5);
        double a = (double)gamma[c] * inv;
        g_bnA[c] = (float)a;
        g_bnB[c] = (float)((double)beta[c] - mu * a);
    }
}

// ---------------- final: out = x + prelu(bn(y)) ----------------
__global__ __launch_bounds__(256) void k_final(const float* __restrict__ x,
                                               const float* __restrict__ oa,
                                               float* __restrict__ out) {
    size_t i4 = ((size_t)blockIdx.x * 256 + threadIdx.x) * 4;
    int c = (int)((i4 >> 13) & 511);
    float a = g_bnA[c], sh = g_bnB[c], pa = __ldg(&oa[c]);
    float4 xv = *(const float4*)(x + i4);
    float4 yv = *(const float4*)(g_y + i4);
    float4 o;
    float t;
    t = fmaf(a, yv.x, sh); o.x = xv.x + (t >= 0.f ? t : pa * t);
    t = fmaf(a, yv.y, sh); o.y = xv.y + (t >= 0.f ? t : pa * t);
    t = fmaf(a, yv.z, sh); o.z = xv.z + (t >= 0.f ? t : pa * t);
    t = fmaf(a, yv.w, sh); o.w = xv.w + (t >= 0.f ? t : pa * t);
    *(float4*)(out + i4) = o;
}

// ---------------- host ----------------
extern "C" void kernel_launch(void* const* d_in, const int* in_sizes, int n_in,
                              void* d_out, int out_size) {
    const float* x     = (const float*)d_in[0];
    const float* cam_w = (const float*)d_in[1];
    const float* cam_b = (const float*)d_in[2];
    const float* w1    = (const float*)d_in[3];
    const float* ga    = (const float*)d_in[4];
    const float* w2    = (const float*)d_in[5];
    const float* fw    = (const float*)d_in[6];
    const float* fb    = (const float*)d_in[7];
    const float* ra    = (const float*)d_in[8];
    const float* qw    = (const float*)d_in[9];
    const float* qb    = (const float*)d_in[10];
    const float* kw    = (const float*)d_in[11];
    const float* kb    = (const float*)d_in[12];
    const float* vw    = (const float*)d_in[13];
    const float* vb    = (const float*)d_in[14];
    const float* ow    = (const float*)d_in[15];
    const float* gam   = (const float*)d_in[16];
    const float* bet   = (const float*)d_in[17];
    const float* oa    = (const float*)d_in[18];
    float* out = (float*)d_out;

    float *p_t, *p_l2, *p_glob, *p_key, *p_qk, *p_val, *p_wv;
    cudaGetSymbolAddress((void**)&p_t,    g_t);
    cudaGetSymbolAddress((void**)&p_l2,   g_l2);
    cudaGetSymbolAddress((void**)&p_glob, g_glob);
    cudaGetSymbolAddress((void**)&p_key,  g_key);
    cudaGetSymbolAddress((void**)&p_qk,   g_qk);
    cudaGetSymbolAddress((void**)&p_val,  g_val);
    cudaGetSymbolAddress((void**)&p_wv,   g_wv);

    k_cam<<<128, 256>>>(x, cam_w, cam_b);
    k_binstats<<<ROWS_, 256>>>();
    k_local<<<128, 256>>>(x);
    k_gcn1<<<(B_ * KC_ + 255) / 256, 256>>>(w1, ga);
    // l2 = t @ w2^T       (M=1216, N=512, K=512)
    k_sgemm<false, false><<<dim3(8, 19), 256>>>(p_t, w2, nullptr, p_l2, ROWS_, 512, 512);
    k_glob<<<(B_ * KC_ + 255) / 256, 256>>>(fw, fb, ra);
    // key = l2 @ k_w^T + k_b   (M=1216, N=256, K=512)
    k_sgemm<false, true><<<dim3(4, 19), 256>>>(p_l2, kw, kb, p_key, ROWS_, 256, 512);
    k_qbk<<<ROWS_, 256>>>(qb);
    // qk = key @ q_w           (M=1216, N=512, K=256; B is [K,N])
    k_sgemm<true, false><<<dim3(8, 19), 256>>>(p_key, qw, nullptr, p_qk, ROWS_, 512, 256);
    // val = glob @ v_w^T + v_b (M=152, N=256, K=512)
    k_sgemm<false, true><<<dim3(4, 3), 256>>>(p_glob, vw, vb, p_val, B_ * K_, 256, 512);
    // wv = val @ out_w^T       (M=152, N=512, K=256)
    k_sgemm<false, false><<<dim3(8, 3), 256>>>(p_val, ow, nullptr, p_wv, B_ * K_, 512, 256);
    cudaFuncSetAttribute(k_attn, cudaFuncAttributeMaxDynamicSharedMemorySize, 2 * KC_ * 4);
    k_attn<<<128, 256, 2 * KC_ * 4>>>(x);
    k_bnstats<<<C_, 256>>>(gam, bet);
    k_final<<<(B_ * C_ * HW_) / 1024, 256>>>(x, oa, out);
}

// round 3
// speedup vs baseline: 1.7094x; 1.7094x over previous
#include <cuda_runtime.h>
#include <math.h>

#define B_ 8
#define C_ 512
#define H_ 64
#define W_ 128
#define K_ 19
#define N_ 8
#define CI_ 256
#define HW_ (H_*W_)       // 8192
#define KC_ (K_*C_)       // 9728
#define ROWS_ (B_*N_*K_)  // 1216
#define NBIN_ (B_*N_)     // 64
#define PBIN_ 1024        // pixels per bin

// ---------------- scratch (static device globals; no allocs) ----------------
__device__ float g_camA[B_*K_*HW_];       // cam partial c<256 (no bias)
__device__ float g_camB[B_*K_*HW_];       // cam partial c>=256
__device__ float g_mx[ROWS_];             // per (b,n,k) max of cam over bin
__device__ float g_coef[ROWS_];           // sigmoid(mean+bias)/sumexp
__device__ float g_local[B_*N_*KC_];
__device__ float g_t[B_*N_*KC_];
__device__ float g_l2[B_*N_*KC_];
__device__ float g_glob[B_*KC_];
__device__ float g_key[ROWS_*CI_];
__device__ float g_qk[B_*N_*KC_];         // [bn,k,c]
__device__ float g_qbk[ROWS_];
__device__ float g_val[B_*K_*CI_];
__device__ float g_wv[B_*KC_];            // [b,k,c]
__device__ float g_partA[NBIN_*K_*PBIN_]; // partial logits c<256  [bn,k,p]
__device__ float g_partB[NBIN_*K_*PBIN_]; // partial logits c>=256
__device__ float g_aff[NBIN_*K_*PBIN_];   // softmax probs [bn,k,p]
__device__ float g_G[NBIN_*K_*K_];        // per-bin Gram of aff
__device__ float g_affsum[NBIN_*K_];
__device__ float g_bnA[C_];
__device__ float g_bnB[C_];

// ---------------- cam partial: 256 blocks = b(8) x chunk(16) x ch(2) ----------------
__global__ __launch_bounds__(256) void k_cam(const float* __restrict__ x,
                                             const float* __restrict__ w) {
    __shared__ float sw[K_*256];
    int blk = blockIdx.x;
    int ch = blk & 1, chunk = (blk >> 1) & 15, b = blk >> 5;
    int tid = threadIdx.x;
    for (int i = tid; i < K_*256; i += 256) {
        int k = i >> 8, c = i & 255;
        sw[i] = w[k * C_ + ch * 256 + c];
    }
    __syncthreads();
    int pix0 = (chunk << 9) + tid;
    const float* xp = x + ((size_t)(b * C_ + ch * 256)) * HW_;
    float a0[K_], a1[K_];
#pragma unroll
    for (int k = 0; k < K_; k++) { a0[k] = 0.f; a1[k] = 0.f; }
#pragma unroll 2
    for (int c = 0; c < 256; c += 2) {
        float x00 = xp[(size_t)c * HW_ + pix0];
        float x01 = xp[(size_t)c * HW_ + pix0 + 256];
        float x10 = xp[(size_t)(c + 1) * HW_ + pix0];
        float x11 = xp[(size_t)(c + 1) * HW_ + pix0 + 256];
#pragma unroll
        for (int k = 0; k < K_; k++) {
            float2 wv = *(const float2*)&sw[k * 256 + c];
            a0[k] = fmaf(wv.x, x00, a0[k]);
            a1[k] = fmaf(wv.x, x01, a1[k]);
            a0[k] = fmaf(wv.y, x10, a0[k]);
            a1[k] = fmaf(wv.y, x11, a1[k]);
        }
    }
    float* outp = (ch ? g_camB : g_camA) + (size_t)b * K_ * HW_ + pix0;
#pragma unroll
    for (int k = 0; k < K_; k++) {
        outp[k * HW_ +   0] = a0[k];
        outp[k * HW_ + 256] = a1[k];
    }
}

// ---------------- per-(b,n,k) bin stats (reads camA+camB, bias here) ----------------
__global__ __launch_bounds__(256) void k_binstats(const float* __restrict__ bias) {
    int idx = blockIdx.x;           // bn*19 + k
    int k = idx % K_;
    int bn = idx / K_;
    int n = bn & 7, b = bn >> 3;
    int bh = n >> 2, bw = n & 3;
    int base = (b * K_ + k) * HW_ + bh * 32 * W_ + bw * 32;
    __shared__ float s[1024];
    __shared__ float red[256];
    int tid = threadIdx.x;
    for (int i = tid; i < 1024; i += 256) {
        int off = base + (i >> 5) * W_ + (i & 31);
        s[i] = g_camA[off] + g_camB[off];
    }
    __syncthreads();
    float sm = 0.f, mx = -1e30f;
    for (int i = tid; i < 1024; i += 256) { float v = s[i]; sm += v; mx = fmaxf(mx, v); }
    red[tid] = sm; __syncthreads();
    for (int o = 128; o > 0; o >>= 1) { if (tid < o) red[tid] += red[tid + o]; __syncthreads(); }
    float total = red[0]; __syncthreads();
    red[tid] = mx; __syncthreads();
    for (int o = 128; o > 0; o >>= 1) { if (tid < o) red[tid] = fmaxf(red[tid], red[tid + o]); __syncthreads(); }
    mx = red[0]; __syncthreads();
    float se = 0.f;
    for (int i = tid; i < 1024; i += 256) se += expf(s[i] - mx);
    red[tid] = se; __syncthreads();
    for (int o = 128; o > 0; o >>= 1) { if (tid < o) red[tid] += red[tid + o]; __syncthreads(); }
    if (tid == 0) {
        float mean = total * (1.f / 1024.f) + bias[k];   // bias only affects cls_score
        float conf = 1.f / (1.f + expf(-mean));
        g_mx[idx] = mx;
        g_coef[idx] = conf / red[0];
    }
}

// ---------------- local[b,n,k,c] = sum_p pixw * x ----------------
__global__ __launch_bounds__(256) void k_local(const float* __restrict__ x) {
    int blk = blockIdx.x;            // 128 blocks: bn*2 + half
    int half = blk & 1, bn = blk >> 1;
    int n = bn & 7, b = bn >> 3;
    int bh = n >> 2, bw = n & 3;
    int c0 = half * 256;
    int tid = threadIdx.x;
    __shared__ float Xs[256 * 34];
    __shared__ float Pe[K_ * 32];
    __shared__ float smx[K_], scf[K_];
    if (tid < K_) { smx[tid] = g_mx[bn * K_ + tid]; scf[tid] = g_coef[bn * K_ + tid]; }
    float acc[K_];
#pragma unroll
    for (int k = 0; k < K_; k++) acc[k] = 0.f;
    const float* xb = x + (size_t)b * C_ * HW_;
    for (int chunk = 0; chunk < 32; chunk++) {
        int rowpix = (bh * 32 + chunk) * W_ + bw * 32;
        __syncthreads();
        for (int i = tid; i < 256 * 32; i += 256) {
            int c = i >> 5, p = i & 31;
            Xs[c * 34 + p] = xb[(size_t)(c0 + c) * HW_ + rowpix + p];
        }
        for (int i = tid; i < K_ * 32; i += 256) {
            int k = i >> 5, p = i & 31;
            int off = (b * K_ + k) * HW_ + rowpix + p;
            Pe[i] = expf(g_camA[off] + g_camB[off] - smx[k]) * scf[k];
        }
        __syncthreads();
#pragma unroll 4
        for (int p = 0; p < 32; p += 2) {
            float2 xv = *(const float2*)&Xs[tid * 34 + p];
#pragma unroll
            for (int k = 0; k < K_; k++) {
                float2 pv = *(const float2*)&Pe[k * 32 + p];
                acc[k] = fmaf(pv.x, xv.x, acc[k]);
                acc[k] = fmaf(pv.y, xv.y, acc[k]);
            }
        }
    }
    float* lp = g_local + (size_t)bn * KC_ + c0 + tid;
#pragma unroll
    for (int k = 0; k < K_; k++) lp[k * C_] = acc[k];
}

// ---------------- GCN conv1 (over bins) + PReLU ----------------
__global__ void k_gcn1(const float* __restrict__ w1, const float* __restrict__ ga) {
    int idx = blockIdx.x * blockDim.x + threadIdx.x;
    if (idx >= B_ * KC_) return;
    int b = idx / KC_, r = idx % KC_;
    float lv[N_];
#pragma unroll
    for (int m = 0; m < N_; m++) lv[m] = g_local[(size_t)(b * N_ + m) * KC_ + r];
#pragma unroll
    for (int nn = 0; nn < N_; nn++) {
        float s = lv[nn];
#pragma unroll
        for (int m = 0; m < N_; m++) s = fmaf(__ldg(&w1[nn * N_ + m]), lv[m], s);
        float a = __ldg(&ga[nn]);
        g_t[(size_t)(b * N_ + nn) * KC_ + r] = s >= 0.f ? s : a * s;
    }
}

// ---------------- generic tiled SGEMM ----------------
template <bool TRANSB, bool HASBIAS>
__global__ __launch_bounds__(256) void k_sgemm(const float* __restrict__ A,
                                               const float* __restrict__ Bm,
                                               const float* __restrict__ bias,
                                               float* __restrict__ Cm,
                                               int M, int N, int K) {
    __shared__ float As[16 * 64];
    __shared__ float Bs[16 * 64];
    int tid = threadIdx.x;
    int bm = blockIdx.y * 64, bn = blockIdx.x * 64;
    int tx = tid & 15, ty = tid >> 4;
    float acc[4][4];
#pragma unroll
    for (int i = 0; i < 4; i++)
#pragma unroll
        for (int j = 0; j < 4; j++) acc[i][j] = 0.f;
    for (int k0 = 0; k0 < K; k0 += 16) {
        {
            int r = tid >> 2, kk = (tid & 3) << 2;
            float4 v = make_float4(0.f, 0.f, 0.f, 0.f);
            if (bm + r < M) v = *(const float4*)&A[(size_t)(bm + r) * K + k0 + kk];
            As[(kk + 0) * 64 + r] = v.x; As[(kk + 1) * 64 + r] = v.y;
            As[(kk + 2) * 64 + r] = v.z; As[(kk + 3) * 64 + r] = v.w;
        }
        if (!TRANSB) {
            int r = tid >> 2, kk = (tid & 3) << 2;
            float4 v = *(const float4*)&Bm[(size_t)(bn + r) * K + k0 + kk];
            Bs[(kk + 0) * 64 + r] = v.x; Bs[(kk + 1) * 64 + r] = v.y;
            Bs[(kk + 2) * 64 + r] = v.z; Bs[(kk + 3) * 64 + r] = v.w;
        } else {
            int kk = tid >> 4, j = (tid & 15) << 2;
            float4 v = *(const float4*)&Bm[(size_t)(k0 + kk) * N + bn + j];
            *(float4*)&Bs[kk * 64 + j] = v;
        }
        __syncthreads();
#pragma unroll
        for (int kk = 0; kk < 16; kk++) {
            float4 a4 = *(const float4*)&As[kk * 64 + ty * 4];
            float4 b4 = *(const float4*)&Bs[kk * 64 + tx * 4];
            float av[4] = {a4.x, a4.y, a4.z, a4.w};
            float bv[4] = {b4.x, b4.y, b4.z, b4.w};
#pragma unroll
            for (int i = 0; i < 4; i++)
#pragma unroll
                for (int j = 0; j < 4; j++) acc[i][j] = fmaf(av[i], bv[j], acc[i][j]);
        }
        __syncthreads();
    }
#pragma unroll
    for (int i = 0; i < 4; i++) {
        int r = bm + ty * 4 + i;
        if (r < M) {
#pragma unroll
            for (int j = 0; j < 4; j++) {
                int cc = bn + tx * 4 + j;
                float v = acc[i][j];
                if (HASBIAS) v += bias[cc];
                Cm[(size_t)r * N + cc] = v;
            }
        }
    }
}

// ---------------- glob = prelu(fuse_w . l2 + fuse_b) ----------------
__global__ void k_glob(const float* __restrict__ fw, const float* __restrict__ fb,
                       const float* __restrict__ ra) {
    int idx = blockIdx.x * blockDim.x + threadIdx.x;
    if (idx >= B_ * KC_) return;
    int b = idx / KC_, r = idx % KC_;
    float s = __ldg(&fb[0]);
#pragma unroll
    for (int nn = 0; nn < N_; nn++)
        s = fmaf(__ldg(&fw[nn]), g_l2[(size_t)(b * N_ + nn) * KC_ + r], s);
    float a = __ldg(&ra[0]);
    g_glob[idx] = s >= 0.f ? s : a * s;
}

// ---------------- qbk[row] = q_b . key[row] ----------------
__global__ __launch_bounds__(256) void k_qbk(const float* __restrict__ qb) {
    int row = blockIdx.x;
    int tid = threadIdx.x;
    __shared__ float red[256];
    red[tid] = qb[tid] * g_key[(size_t)row * CI_ + tid];
    __syncthreads();
    for (int o = 128; o > 0; o >>= 1) { if (tid < o) red[tid] += red[tid + o]; __syncthreads(); }
    if (tid == 0) g_qbk[row] = red[0];
}

// ---------------- attn stage 1: partial logits over channel half ----------------
// 256 blocks = bn(64) x ch(2) x ph(2)
__global__ __launch_bounds__(256) void k_attn1(const float* __restrict__ x) {
    __shared__ float sqk[K_*256];
    int blk = blockIdx.x;
    int ph = blk & 1, ch = (blk >> 1) & 1, bn = blk >> 2;
    int n = bn & 7, b = bn >> 3;
    int bh = n >> 2, bw = n & 3;
    int tid = threadIdx.x;
    for (int i = tid; i < K_*256; i += 256) {
        int k = i >> 8, c = i & 255;
        sqk[i] = g_qk[(size_t)(bn * K_ + k) * C_ + ch * 256 + c];
    }
    __syncthreads();
    int p0 = ph * 512 + tid;
    int pix0 = (bh * 32 + (p0 >> 5)) * W_ + bw * 32 + (p0 & 31);
    int pix1 = pix0 + 1024;       // bin pixel p0+256
    const float* xb = x + ((size_t)(b * C_ + ch * 256)) * HW_;
    float l0[K_], l1[K_];
#pragma unroll
    for (int k = 0; k < K_; k++) { l0[k] = 0.f; l1[k] = 0.f; }
#pragma unroll 2
    for (int c = 0; c < 256; c += 2) {
        float x00 = xb[(size_t)c * HW_ + pix0];
        float x01 = xb[(size_t)c * HW_ + pix1];
        float x10 = xb[(size_t)(c + 1) * HW_ + pix0];
        float x11 = xb[(size_t)(c + 1) * HW_ + pix1];
#pragma unroll
        for (int k = 0; k < K_; k++) {
            float2 wv = *(const float2*)&sqk[k * 256 + c];
            l0[k] = fmaf(wv.x, x00, l0[k]);
            l1[k] = fmaf(wv.x, x01, l1[k]);
            l0[k] = fmaf(wv.y, x10, l0[k]);
            l1[k] = fmaf(wv.y, x11, l1[k]);
        }
    }
    float* pp = (ch ? g_partB : g_partA) + (size_t)bn * K_ * PBIN_;
#pragma unroll
    for (int k = 0; k < K_; k++) {
        pp[k * PBIN_ + p0]       = l0[k];
        pp[k * PBIN_ + p0 + 256] = l1[k];
    }
}

// ---------------- attn stage 2: combine + softmax -> aff ----------------
// 256 blocks = bn(64) x quarter(4), 256 px each
__global__ __launch_bounds__(256) void k_attn2() {
    int blk = blockIdx.x;
    int q = blk & 3, bn = blk >> 2;
    int p = q * 256 + threadIdx.x;
    __shared__ float sqb[K_];
    if (threadIdx.x < K_) sqb[threadIdx.x] = g_qbk[bn * K_ + threadIdx.x];
    __syncthreads();
    size_t base = (size_t)bn * K_ * PBIN_ + p;
    float l[K_];
#pragma unroll
    for (int k = 0; k < K_; k++)
        l[k] = g_partA[base + k * PBIN_] + g_partB[base + k * PBIN_] + sqb[k];
    float m = l[0];
#pragma unroll
    for (int k = 1; k < K_; k++) m = fmaxf(m, l[k]);
    float s = 0.f;
#pragma unroll
    for (int k = 0; k < K_; k++) { l[k] = expf(l[k] - m); s += l[k]; }
    float inv = 1.f / s;
#pragma unroll
    for (int k = 0; k < K_; k++) g_aff[base + k * PBIN_] = l[k] * inv;
}

// ---------------- Gram: G[bn,k,k'] = sum_p aff_k aff_k'; affsum ----------------
#define PPAD_ 1028
extern __shared__ float s_aff[];   // K_*PPAD_ floats (~78KB)
__global__ __launch_bounds__(256) void k_gram() {
    int bn = blockIdx.x;
    int tid = threadIdx.x;
    for (int i = tid; i < K_ * PBIN_; i += 256) {
        int k = i / PBIN_, p = i % PBIN_;
        s_aff[k * PPAD_ + p] = g_aff[(size_t)bn * K_ * PBIN_ + i];
    }
    __syncthreads();
    if (tid < 190) {
        // pair (k <= k2) from triangular index
        int k = 0, t = tid;
        while (t >= K_ - k) { t -= (K_ - k); k++; }
        int k2 = k + t;
        const float* pa = &s_aff[k * PPAD_];
        const float* pb = &s_aff[k2 * PPAD_];
        float acc = 0.f;
#pragma unroll 4
        for (int p = 0; p < PBIN_; p += 4) {
            float4 a = *(const float4*)&pa[p];
            float4 b = *(const float4*)&pb[p];
            acc = fmaf(a.x, b.x, acc);
            acc = fmaf(a.y, b.y, acc);
            acc = fmaf(a.z, b.z, acc);
            acc = fmaf(a.w, b.w, acc);
        }
        g_G[(bn * K_ + k) * K_ + k2] = acc;
        g_G[(bn * K_ + k2) * K_ + k] = acc;
    } else if (tid >= 192 && tid < 192 + K_) {
        int k = tid - 192;
        const float* pa = &s_aff[k * PPAD_];
        float acc = 0.f;
#pragma unroll 4
        for (int p = 0; p < PBIN_; p += 4) {
            float4 a = *(const float4*)&pa[p];
            acc += a.x + a.y + a.z + a.w;
        }
        g_affsum[bn * K_ + k] = acc;
    }
}

// ---------------- BN coefficients from Gram algebra ----------------
// 512 blocks (c), 64 threads (bn)
__global__ __launch_bounds__(64) void k_bnab(const float* __restrict__ gamma,
                                             const float* __restrict__ beta) {
    int c = blockIdx.x;
    int bn = threadIdx.x;
    int b = bn >> 3;
    float w[K_];
#pragma unroll
    for (int k = 0; k < K_; k++) w[k] = g_wv[(size_t)(b * K_ + k) * C_ + c];
    float s1 = 0.f, s2 = 0.f;
#pragma unroll
    for (int k = 0; k < K_; k++) {
        s1 = fmaf(g_affsum[bn * K_ + k], w[k], s1);
        float inner = 0.f;
#pragma unroll
        for (int k2 = 0; k2 < K_; k2++)
            inner = fmaf(g_G[(bn * K_ + k) * K_ + k2], w[k2], inner);
        s2 = fmaf(inner, w[k], s2);
    }
    __shared__ double r1[64], r2[64];
    r1[bn] = (double)s1; r2[bn] = (double)s2;
    __syncthreads();
    for (int o = 32; o > 0; o >>= 1) {
        if (bn < o) { r1[bn] += r1[bn + o]; r2[bn] += r2[bn + o]; }
        __syncthreads();
    }
    if (bn == 0) {
        double cnt = (double)(B_ * HW_);
        double mu = r1[0] / cnt;
        double ey2 = r2[0] / cnt;
        double var = ey2 - mu * mu;
        double inv = 1.0 / sqrt(var + 1e-5);
        double a = (double)gamma[c] * inv;
        g_bnA[c] = (float)a;
        g_bnB[c] = (float)((double)beta[c] - mu * a);
    }
}

// ---------------- final: out = x + prelu(bnA*(aff.wv) + bnB) ----------------
// 256 blocks = bn(64) x ch(2) x ph(2)
__global__ __launch_bounds__(256) void k_final(const float* __restrict__ x,
                                               const float* __restrict__ oa,
                                               float* __restrict__ out) {
    __shared__ float swv[K_*256];
    __shared__ float sB[256], sOa[256];
    int blk = blockIdx.x;
    int ph = blk & 1, ch = (blk >> 1) & 1, bn = blk >> 2;
    int n = bn & 7, b = bn >> 3;
    int bh = n >> 2, bw = n & 3;
    int c0 = ch * 256;
    int tid = threadIdx.x;
    for (int i = tid; i < K_*256; i += 256) {
        int k = i >> 8, c = i & 255;
        swv[i] = g_bnA[c0 + c] * g_wv[(size_t)(b * K_ + k) * C_ + c0 + c];
    }
    if (tid < 256) { sB[tid] = g_bnB[c0 + tid]; sOa[tid] = oa[c0 + tid]; }
    __syncthreads();
    int p0 = ph * 512 + tid;
    int pix0 = (bh * 32 + (p0 >> 5)) * W_ + bw * 32 + (p0 & 31);
    int pix1 = pix0 + 1024;
    float a0[K_], a1[K_];
    const float* ap = g_aff + (size_t)bn * K_ * PBIN_;
#pragma unroll
    for (int k = 0; k < K_; k++) {
        a0[k] = ap[k * PBIN_ + p0];
        a1[k] = ap[k * PBIN_ + p0 + 256];
    }
    const float* xb = x + ((size_t)(b * C_ + c0)) * HW_;
    float* ob = out + ((size_t)(b * C_ + c0)) * HW_;
#pragma unroll 2
    for (int c = 0; c < 256; c += 2) {
        float y00 = 0.f, y01 = 0.f, y10 = 0.f, y11 = 0.f;
#pragma unroll
        for (int k = 0; k < K_; k++) {
            float2 wv = *(const float2*)&swv[k * 256 + c];
            y00 = fmaf(a0[k], wv.x, y00);
            y01 = fmaf(a1[k], wv.x, y01);
            y10 = fmaf(a0[k], wv.y, y10);
            y11 = fmaf(a1[k], wv.y, y11);
        }
        float b0 = sB[c], b1 = sB[c + 1];
        float p0a = sOa[c], p1a = sOa[c + 1];
        float t;
        t = y00 + b0; ob[(size_t)c * HW_ + pix0]       = xb[(size_t)c * HW_ + pix0]       + (t >= 0.f ? t : p0a * t);
        t = y01 + b0; ob[(size_t)c * HW_ + pix1]       = xb[(size_t)c * HW_ + pix1]       + (t >= 0.f ? t : p0a * t);
        t = y10 + b1; ob[(size_t)(c+1) * HW_ + pix0]   = xb[(size_t)(c+1) * HW_ + pix0]   + (t >= 0.f ? t : p1a * t);
        t = y11 + b1; ob[(size_t)(c+1) * HW_ + pix1]   = xb[(size_t)(c+1) * HW_ + pix1]   + (t >= 0.f ? t : p1a * t);
    }
}

// ---------------- host ----------------
extern "C" void kernel_launch(void* const* d_in, const int* in_sizes, int n_in,
                              void* d_out, int out_size) {
    const float* x     = (const float*)d_in[0];
    const float* cam_w = (const float*)d_in[1];
    const float* cam_b = (const float*)d_in[2];
    const float* w1    = (const float*)d_in[3];
    const float* ga    = (const float*)d_in[4];
    const float* w2    = (const float*)d_in[5];
    const float* fw    = (const float*)d_in[6];
    const float* fb    = (const float*)d_in[7];
    const float* ra    = (const float*)d_in[8];
    const float* qw    = (const float*)d_in[9];
    const float* qb    = (const float*)d_in[10];
    const float* kw    = (const float*)d_in[11];
    const float* kb    = (const float*)d_in[12];
    const float* vw    = (const float*)d_in[13];
    const float* vb    = (const float*)d_in[14];
    const float* ow    = (const float*)d_in[15];
    const float* gam   = (const float*)d_in[16];
    const float* bet   = (const float*)d_in[17];
    const float* oa    = (const float*)d_in[18];
    float* out = (float*)d_out;

    float *p_t, *p_l2, *p_glob, *p_key, *p_qk, *p_val, *p_wv;
    cudaGetSymbolAddress((void**)&p_t,    g_t);
    cudaGetSymbolAddress((void**)&p_l2,   g_l2);
    cudaGetSymbolAddress((void**)&p_glob, g_glob);
    cudaGetSymbolAddress((void**)&p_key,  g_key);
    cudaGetSymbolAddress((void**)&p_qk,   g_qk);
    cudaGetSymbolAddress((void**)&p_val,  g_val);
    cudaGetSymbolAddress((void**)&p_wv,   g_wv);

    k_cam<<<256, 256>>>(x, cam_w);
    k_binstats<<<ROWS_, 256>>>(cam_b);
    k_local<<<128, 256>>>(x);
    k_gcn1<<<(B_ * KC_ + 255) / 256, 256>>>(w1, ga);
    k_sgemm<false, false><<<dim3(8, 19), 256>>>(p_t, w2, nullptr, p_l2, ROWS_, 512, 512);
    k_glob<<<(B_ * KC_ + 255) / 256, 256>>>(fw, fb, ra);
    k_sgemm<false, true><<<dim3(4, 19), 256>>>(p_l2, kw, kb, p_key, ROWS_, 256, 512);
    k_qbk<<<ROWS_, 256>>>(qb);
    k_sgemm<true, false><<<dim3(8, 19), 256>>>(p_key, qw, nullptr, p_qk, ROWS_, 512, 256);
    k_sgemm<false, true><<<dim3(4, 3), 256>>>(p_glob, vw, vb, p_val, B_ * K_, 256, 512);
    k_sgemm<false, false><<<dim3(8, 3), 256>>>(p_val, ow, nullptr, p_wv, B_ * K_, 512, 256);
    k_attn1<<<256, 256>>>(x);
    k_attn2<<<256, 256>>>();
    cudaFuncSetAttribute(k_gram, cudaFuncAttributeMaxDynamicSharedMemorySize, K_ * PPAD_ * 4);
    k_gram<<<NBIN_, 256, K_ * PPAD_ * 4>>>();
    k_bnab<<<C_, 64>>>(gam, bet);
    k_final<<<256, 256>>>(x, oa, out);
}